// round 17
// baseline (speedup 1.0000x reference)
#include <cuda_runtime.h>
#include <cuda_fp16.h>
#include <cstdint>

#define NS 16
#define CT 256
#define TAPS 64
#define PLANE 3969
#define PPAD 4096
#define MT 128
#define PTILES 32
#define MOUT 56
#define OUTN (MOUT * MOUT)
#define NCTA 296
#define NTILE (NS * PTILES)      // 512
#define CHUNKS_PER_N 98          // 3136/32
#define NCHUNK (NS * CHUNKS_PER_N)  // 1568

#define SM_A 0
#define SM_B 65536
#define SM_RED 98304
#define SMEM_TOTAL (98304 + 1024)

__device__ __half g_Dt[(size_t)NS * TAPS * PPAD];   // 8.4 MB, [n][tap][pos]
__device__ unsigned g_cnt[NS];                       // monotonic tile-done counters
__device__ unsigned g_rep[NCTA];                     // per-CTA replay index

__device__ __forceinline__ float fast_sqrt(float v) {
    float r; asm("sqrt.approx.f32 %0, %1;" : "=f"(r) : "f"(v)); return r;
}
__device__ __forceinline__ uint32_t swz(int m, int cb) {
    return (uint32_t)(m * 512 + (cb ^ ((m & 7) << 4)));
}
__device__ __forceinline__ void ldsm_x4(uint32_t* r, uint32_t addr) {
    asm volatile("ldmatrix.sync.aligned.m8n8.x4.shared.b16 {%0,%1,%2,%3}, [%4];"
                 : "=r"(r[0]), "=r"(r[1]), "=r"(r[2]), "=r"(r[3]) : "r"(addr));
}
__device__ __forceinline__ void mma16816(float* d, const uint32_t* a, const uint32_t* b) {
    asm volatile("mma.sync.aligned.m16n8k16.row.col.f32.f16.f16.f32 "
                 "{%0,%1,%2,%3}, {%4,%5,%6,%7}, {%8,%9}, {%0,%1,%2,%3};"
                 : "+f"(d[0]), "+f"(d[1]), "+f"(d[2]), "+f"(d[3])
                 : "r"(a[0]), "r"(a[1]), "r"(a[2]), "r"(a[3]), "r"(b[0]), "r"(b[1]));
}

__global__ __launch_bounds__(256, 2)
void fused_kernel(const float* __restrict__ z, const float* __restrict__ x,
                  const float* __restrict__ w, float* __restrict__ out)
{
    extern __shared__ char smem[];
    const uint32_t sb = (uint32_t)__cvta_generic_to_shared(smem);
    float* red = reinterpret_cast<float*>(smem + SM_RED);
    const int tid = threadIdx.x, wid = tid >> 5, lid = tid & 31;
    const int b = blockIdx.x;

    unsigned repR = 0;
    if (tid == 0) { repR = g_rep[b]; g_rep[b] = repR + 1; }

    // fragment selectors (R15, validated)
    const int m_base = wid * 16;
    const int a_m  = m_base + ((lid >> 3) & 1) * 8 + (lid & 7);
    const int a_cs = ((lid >> 4) & 1) * 16;
    const int b_t8 = ((lid >> 4) & 1) * 8 + (lid & 7);
    const int b_cs = ((lid >> 3) & 1) * 16;

    // ================= GEMM phase: static tiles b, b+296 =================
    #pragma unroll 1
    for (int t = b; t < NTILE; t += NCTA) {
        const int n = t >> 5, tile = t & 31;
        const int pos0 = (tile == PTILES - 1) ? (PLANE - MT) : tile * MT;
        const float* xn = x + (size_t)n * CT * PLANE;
        const float* zn = z + (size_t)n * CT * TAPS;

        __syncthreads();   // smem safe to overwrite (prev tile's ldsm done)

        // ---- stage A = f16(sqrt(x)) : 128 pos x 256 ch ----
        #pragma unroll 16
        for (int it = 0; it < 64; it++) {
            int pidx = it * 256 + tid;
            int m = pidx & 127, c0 = (pidx >> 7) * 2;
            float f0 = fast_sqrt(xn[(size_t)c0 * PLANE + pos0 + m]);
            float f1 = fast_sqrt(xn[(size_t)(c0 + 1) * PLANE + pos0 + m]);
            uint32_t v; asm("cvt.rn.f16x2.f32 %0, %1, %2;" : "=r"(v) : "f"(f1), "f"(f0));
            asm volatile("st.shared.b32 [%0], %1;"
                         :: "r"(sb + SM_A + swz(m, c0 * 2)), "r"(v));
        }
        // ---- stage B = f16(w*sqrt(z)) : 64 taps x 256 ch ----
        #pragma unroll 8
        for (int it = 0; it < 32; it++) {
            int pidx = it * 256 + tid;
            int tp = pidx & 63, c0 = (pidx >> 6) * 2;
            float f0 = w[c0]     * fast_sqrt(zn[(size_t)c0 * TAPS + tp]);
            float f1 = w[c0 + 1] * fast_sqrt(zn[(size_t)(c0 + 1) * TAPS + tp]);
            uint32_t v; asm("cvt.rn.f16x2.f32 %0, %1, %2;" : "=r"(v) : "f"(f1), "f"(f0));
            asm volatile("st.shared.b32 [%0], %1;"
                         :: "r"(sb + SM_B + swz(tp, c0 * 2)), "r"(v));
        }
        __syncthreads();

        // ---- mainloop ----
        float acc[8][4];
        #pragma unroll
        for (int nb = 0; nb < 8; nb++)
            #pragma unroll
            for (int e = 0; e < 4; e++) acc[nb][e] = 0.0f;

        #pragma unroll
        for (int ks = 0; ks < 16; ks++) {
            uint32_t a[4];
            ldsm_x4(a, sb + SM_A + swz(a_m, ks * 32 + a_cs));
            #pragma unroll
            for (int jp = 0; jp < 4; jp++) {
                uint32_t bf[4];
                int bt = jp * 16 + b_t8;
                ldsm_x4(bf, sb + SM_B + swz(bt, ks * 32 + b_cs));
                mma16816(acc[2 * jp],     a, bf);
                mma16816(acc[2 * jp + 1], a, bf + 2);
            }
        }

        // ---- writeback (R11 direct scatter) ----
        __half* dst = g_Dt + (size_t)n * TAPS * PPAD;
        const int mr = m_base + (lid >> 2);
        const int tc = 2 * (lid & 3);
        #pragma unroll
        for (int nb = 0; nb < 8; nb++) {
            int t0 = nb * 8 + tc;
            dst[(size_t)t0 * PPAD + pos0 + mr]           = __float2half_rn(acc[nb][0]);
            dst[(size_t)(t0 + 1) * PPAD + pos0 + mr]     = __float2half_rn(acc[nb][1]);
            dst[(size_t)t0 * PPAD + pos0 + mr + 8]       = __float2half_rn(acc[nb][2]);
            dst[(size_t)(t0 + 1) * PPAD + pos0 + mr + 8] = __float2half_rn(acc[nb][3]);
        }

        // ---- release: tile done ----
        __threadfence();
        __syncthreads();
        if (tid == 0) atomicAdd(&g_cnt[n], 1u);
    }

    // ================= epilogue phase: static chunks =================
    #pragma unroll 1
    for (int c = b; c < NCHUNK; c += NCTA) {
        const int n = c / CHUNKS_PER_N;
        const int local = c - n * CHUNKS_PER_N;

        __syncthreads();                    // red[] reuse across chunks
        if (tid == 0) {
            unsigned target = repR * 32u + 32u;
            while ((int)(*(volatile unsigned*)&g_cnt[n] - target) < 0)
                __nanosleep(256);
            __threadfence();                // acquire
        }
        __syncthreads();

        const int jj = tid & 31, grp = tid >> 5;
        const int r = local * 32 + jj;      // within-sample output index
        const int i = r / MOUT, j = r - i * MOUT;
        // taps t = grp*8+k: p = grp, q = k  =>  offset = grp*(8*PPAD+63) + k*(PPAD+1)
        const __half* base = g_Dt + (size_t)n * TAPS * PPAD + i * 63 + j
                           + (size_t)grp * (8 * PPAD + 63);
        float v[8];
        #pragma unroll
        for (int k = 0; k < 8; k++)
            v[k] = __half2float(base[(size_t)k * (PPAD + 1)]);
        #pragma unroll
        for (int s = 4; s >= 1; s >>= 1)
            #pragma unroll
            for (int k = 0; k < s; k++)
                v[k] += v[k + s];

        red[tid] = v[0];
        __syncthreads();
        if (tid < 128) red[tid] += red[tid + 128];
        __syncthreads();
        if (tid < 64)  red[tid] += red[tid + 64];
        __syncthreads();
        if (tid < 32)
            out[n * OUTN + local * 32 + tid] =
                (red[tid] + red[tid + 32]) * (1.0f / 64.0f);
    }
}

extern "C" void kernel_launch(void* const* d_in, const int* in_sizes, int n_in,
                              void* d_out, int out_size)
{
    const float* z = (const float*)d_in[0];   // (16,256,8,8)
    const float* x = (const float*)d_in[1];   // (16,256,63,63)
    const float* w = (const float*)d_in[2];   // (1,256,1,1,1)
    float* out = (float*)d_out;               // (16,1,56,56)

    cudaFuncSetAttribute(fused_kernel,
                         cudaFuncAttributeMaxDynamicSharedMemorySize, SMEM_TOTAL);
    fused_kernel<<<NCTA, 256, SMEM_TOTAL>>>(z, x, w, out);
}